// round 2
// baseline (speedup 1.0000x reference)
#include <cuda_runtime.h>
#include <math.h>

#define BATCH 1024
#define TSTEPS 32
#define HID 128
#define GATESZ 512
#define FEATSZ 4608
#define ACTD 26

// ---------------- device scratch (no allocations allowed) ----------------
__device__ float g_msk[BATCH * 900];        // current mask
__device__ float g_h[BATCH * HID];          // LSTM hidden
__device__ float g_c[BATCH * HID];          // LSTM cell
__device__ float g_feat[BATCH * FEATSZ];    // conv output features
__device__ float g_gates[BATCH * GATESZ];   // pre-activation gates
__device__ float g_w1t[FEATSZ * GATESZ];    // w_ih transposed -> [k][n]
__device__ float g_w2t[HID * GATESZ];       // w_hh transposed -> [k][n]
__device__ float g_wmt[HID * 900];          // msk_w transposed -> [k][n]

__device__ __forceinline__ float sigf(float x) { return 1.f / (1.f + expf(-x)); }

// ---------------- init state ----------------
__global__ void init_state() {
    int i = blockIdx.x * blockDim.x + threadIdx.x;
    if (i < BATCH * 900) g_msk[i] = 1.f;
    if (i < BATCH * HID) { g_h[i] = 0.f; g_c[i] = 0.f; }
}

// ---------------- weight transposes (run each replay, tiny) ----------------
__global__ void transpose_wih(const float* __restrict__ w) {
    int i = blockIdx.x * 256 + threadIdx.x;     // FEATSZ*GATESZ total
    int k = i / GATESZ, n = i % GATESZ;
    g_w1t[i] = w[n * FEATSZ + k];
}
__global__ void transpose_whh(const float* __restrict__ w) {
    int i = blockIdx.x * 256 + threadIdx.x;
    if (i < HID * GATESZ) {
        int k = i / GATESZ, n = i % GATESZ;
        g_w2t[i] = w[n * HID + k];
    }
}
__global__ void transpose_wm(const float* __restrict__ w) {
    int i = blockIdx.x * 256 + threadIdx.x;
    if (i < HID * 900) {
        int k = i / 900, n = i % 900;
        g_wmt[i] = w[n * HID + k];
    }
}

// ---------------- fused mask-multiply + conv1/2/3 (+ReLU) ----------------
// One block per sample. SMEM holds masked input + both intermediates.
// Warp w owns output channel w. Lane owns one output column; row accumulators
// live in registers (all loop bounds constant -> fully unrolled).
__global__ void conv_kernel(const float* __restrict__ batch,
                            const float* __restrict__ c1w, const float* __restrict__ c1b,
                            const float* __restrict__ c2w, const float* __restrict__ c2b,
                            const float* __restrict__ c3w, const float* __restrict__ c3b) {
    extern __shared__ float sm[];
    float* s_in = sm;                 // 900
    float* s_t1 = sm + 900;           // 8*28*28 = 6272
    float* s_t2 = s_t1 + 6272;        // 8*26*26 = 5408
    float* s_w2 = s_t2 + 5408;        // 576
    float* s_w3 = s_w2 + 576;         // 576

    const int b = blockIdx.x;
    const int tid = threadIdx.x;

    for (int i = tid; i < 900; i += 256) s_in[i] = batch[b * 900 + i] * g_msk[b * 900 + i];
    for (int i = tid; i < 576; i += 256) { s_w2[i] = c2w[i]; s_w3[i] = c3w[i]; }
    __syncthreads();

    const int oc = tid >> 5;       // warp id = output channel
    const int lane = tid & 31;

    // ---- conv1: 1x30x30 -> 8x28x28 ----
    {
        float acc[28];
        float bias = c1b[oc];
#pragma unroll
        for (int r = 0; r < 28; r++) acc[r] = bias;
        float w[9];
#pragma unroll
        for (int i = 0; i < 9; i++) w[i] = c1w[oc * 9 + i];
        if (lane < 28) {
#pragma unroll
            for (int rr = 0; rr < 30; rr++) {
                float i0 = s_in[rr * 30 + lane];
                float i1 = s_in[rr * 30 + lane + 1];
                float i2 = s_in[rr * 30 + lane + 2];
#pragma unroll
                for (int dr = 0; dr < 3; dr++) {
                    int r = rr - dr;
                    if (r >= 0 && r < 28)
                        acc[r] += i0 * w[dr * 3] + i1 * w[dr * 3 + 1] + i2 * w[dr * 3 + 2];
                }
            }
#pragma unroll
            for (int r = 0; r < 28; r++)
                s_t1[oc * 784 + r * 28 + lane] = fmaxf(acc[r], 0.f);
        }
    }
    __syncthreads();

    // ---- conv2: 8x28x28 -> 8x26x26 ----
    {
        float acc[26];
        float bias = c2b[oc];
#pragma unroll
        for (int r = 0; r < 26; r++) acc[r] = bias;
        if (lane < 26) {
            for (int ic = 0; ic < 8; ic++) {
                float w[9];
#pragma unroll
                for (int i = 0; i < 9; i++) w[i] = s_w2[(oc * 8 + ic) * 9 + i];
                const float* inb = s_t1 + ic * 784;
#pragma unroll
                for (int rr = 0; rr < 28; rr++) {
                    float i0 = inb[rr * 28 + lane];
                    float i1 = inb[rr * 28 + lane + 1];
                    float i2 = inb[rr * 28 + lane + 2];
#pragma unroll
                    for (int dr = 0; dr < 3; dr++) {
                        int r = rr - dr;
                        if (r >= 0 && r < 26)
                            acc[r] += i0 * w[dr * 3] + i1 * w[dr * 3 + 1] + i2 * w[dr * 3 + 2];
                    }
                }
            }
#pragma unroll
            for (int r = 0; r < 26; r++)
                s_t2[oc * 676 + r * 26 + lane] = fmaxf(acc[r], 0.f);
        }
    }
    __syncthreads();

    // ---- conv3: 8x26x26 -> 8x24x24 -> g_feat ----
    {
        float acc[24];
        float bias = c3b[oc];
#pragma unroll
        for (int r = 0; r < 24; r++) acc[r] = bias;
        if (lane < 24) {
            for (int ic = 0; ic < 8; ic++) {
                float w[9];
#pragma unroll
                for (int i = 0; i < 9; i++) w[i] = s_w3[(oc * 8 + ic) * 9 + i];
                const float* inb = s_t2 + ic * 676;
#pragma unroll
                for (int rr = 0; rr < 26; rr++) {
                    float i0 = inb[rr * 26 + lane];
                    float i1 = inb[rr * 26 + lane + 1];
                    float i2 = inb[rr * 26 + lane + 2];
#pragma unroll
                    for (int dr = 0; dr < 3; dr++) {
                        int r = rr - dr;
                        if (r >= 0 && r < 24)
                            acc[r] += i0 * w[dr * 3] + i1 * w[dr * 3 + 1] + i2 * w[dr * 3 + 2];
                    }
                }
            }
#pragma unroll
            for (int r = 0; r < 24; r++)
                g_feat[(size_t)b * FEATSZ + oc * 576 + r * 24 + lane] = fmaxf(acc[r], 0.f);
        }
    }
}

// ---------------- gates GEMM: [1024,512] = feat@w1t + h@w2t ----------------
// 64x64 tile per block, 256 threads, 4x4 per thread, K-chunks of 32.
__global__ void gates_gemm() {
    __shared__ float As[32][65];   // [k][m], padded (conflict-free transpose store)
    __shared__ float Bs[32][64];   // [k][n]
    const int tid = threadIdx.x;
    const int n0 = blockIdx.x * 64, m0 = blockIdx.y * 64;
    const int tx = tid & 15, ty = tid >> 4;
    float acc[4][4] = {};

    for (int pass = 0; pass < 2; pass++) {
        const float* __restrict__ A = pass ? g_h : g_feat;
        const float* __restrict__ Bt = pass ? g_w2t : g_w1t;
        const int K = pass ? HID : FEATSZ;
        for (int k0 = 0; k0 < K; k0 += 32) {
            __syncthreads();
#pragma unroll
            for (int i = 0; i < 2; i++) {
                int m = (tid >> 3) + i * 32;
                int kk = (tid & 7) * 4;
                float4 v = *(const float4*)(A + (size_t)(m0 + m) * K + k0 + kk);
                As[kk + 0][m] = v.x; As[kk + 1][m] = v.y;
                As[kk + 2][m] = v.z; As[kk + 3][m] = v.w;
            }
#pragma unroll
            for (int i = 0; i < 2; i++) {
                int kk = (tid >> 4) + i * 16;
                int nn = (tid & 15) * 4;
                *(float4*)&Bs[kk][nn] = *(const float4*)(Bt + (size_t)(k0 + kk) * GATESZ + n0 + nn);
            }
            __syncthreads();
#pragma unroll
            for (int k = 0; k < 32; k++) {
                float a0 = As[k][ty * 4 + 0], a1 = As[k][ty * 4 + 1];
                float a2 = As[k][ty * 4 + 2], a3 = As[k][ty * 4 + 3];
                float4 bv = *(const float4*)&Bs[k][tx * 4];
                acc[0][0] += a0 * bv.x; acc[0][1] += a0 * bv.y; acc[0][2] += a0 * bv.z; acc[0][3] += a0 * bv.w;
                acc[1][0] += a1 * bv.x; acc[1][1] += a1 * bv.y; acc[1][2] += a1 * bv.z; acc[1][3] += a1 * bv.w;
                acc[2][0] += a2 * bv.x; acc[2][1] += a2 * bv.y; acc[2][2] += a2 * bv.z; acc[2][3] += a2 * bv.w;
                acc[3][0] += a3 * bv.x; acc[3][1] += a3 * bv.y; acc[3][2] += a3 * bv.z; acc[3][3] += a3 * bv.w;
            }
        }
    }
#pragma unroll
    for (int i = 0; i < 4; i++)
#pragma unroll
        for (int j = 0; j < 4; j++)
            g_gates[(size_t)(m0 + ty * 4 + i) * GATESZ + n0 + tx * 4 + j] = acc[i][j];
}

// ---------------- LSTM pointwise ----------------
__global__ void lstm_pw(const float* __restrict__ b_ih, const float* __restrict__ b_hh) {
    int idx = blockIdx.x * blockDim.x + threadIdx.x;   // BATCH*HID
    int b = idx >> 7, j = idx & 127;
    const float* g = g_gates + (size_t)b * GATESZ;
    float gi = g[j]        + b_ih[j]        + b_hh[j];
    float gf = g[128 + j]  + b_ih[128 + j]  + b_hh[128 + j];
    float gg = g[256 + j]  + b_ih[256 + j]  + b_hh[256 + j];
    float go = g[384 + j]  + b_ih[384 + j]  + b_hh[384 + j];
    float cn = sigf(gf) * g_c[idx] + sigf(gi) * tanhf(gg);
    g_c[idx] = cn;
    g_h[idx] = sigf(go) * tanhf(cn);
}

// ---------------- mask head GEMM + sigmoid: [1024,900] = h@wmt ----------------
__global__ void mask_gemm(const float* __restrict__ msk_b, float* __restrict__ out_msks, int t) {
    __shared__ float As[32][65];
    __shared__ float Bs[32][64];
    const int tid = threadIdx.x;
    const int n0 = blockIdx.x * 64, m0 = blockIdx.y * 64;
    const int tx = tid & 15, ty = tid >> 4;
    float acc[4][4] = {};

    for (int k0 = 0; k0 < HID; k0 += 32) {
        __syncthreads();
#pragma unroll
        for (int i = 0; i < 2; i++) {
            int m = (tid >> 3) + i * 32;
            int kk = (tid & 7) * 4;
            float4 v = *(const float4*)(g_h + (size_t)(m0 + m) * HID + k0 + kk);
            As[kk + 0][m] = v.x; As[kk + 1][m] = v.y;
            As[kk + 2][m] = v.z; As[kk + 3][m] = v.w;
        }
#pragma unroll
        for (int i = 0; i < 2; i++) {
            int kk = (tid >> 4) + i * 16;
            int nn = (tid & 15) * 4;
            float4 v = make_float4(0.f, 0.f, 0.f, 0.f);
            if (n0 + nn < 900)
                v = *(const float4*)(g_wmt + (size_t)(k0 + kk) * 900 + n0 + nn);
            *(float4*)&Bs[kk][nn] = v;
        }
        __syncthreads();
#pragma unroll
        for (int k = 0; k < 32; k++) {
            float a0 = As[k][ty * 4 + 0], a1 = As[k][ty * 4 + 1];
            float a2 = As[k][ty * 4 + 2], a3 = As[k][ty * 4 + 3];
            float4 bv = *(const float4*)&Bs[k][tx * 4];
            acc[0][0] += a0 * bv.x; acc[0][1] += a0 * bv.y; acc[0][2] += a0 * bv.z; acc[0][3] += a0 * bv.w;
            acc[1][0] += a1 * bv.x; acc[1][1] += a1 * bv.y; acc[1][2] += a1 * bv.z; acc[1][3] += a1 * bv.w;
            acc[2][0] += a2 * bv.x; acc[2][1] += a2 * bv.y; acc[2][2] += a2 * bv.z; acc[2][3] += a2 * bv.w;
            acc[3][0] += a3 * bv.x; acc[3][1] += a3 * bv.y; acc[3][2] += a3 * bv.z; acc[3][3] += a3 * bv.w;
        }
    }
#pragma unroll
    for (int i = 0; i < 4; i++) {
#pragma unroll
        for (int j = 0; j < 4; j++) {
            int m = m0 + ty * 4 + i;
            int n = n0 + tx * 4 + j;
            if (n < 900) {
                float v = sigf(acc[i][j] + msk_b[n]);
                g_msk[(size_t)m * 900 + n] = v;
                out_msks[((size_t)m * TSTEPS + t) * 900 + n] = v;
            }
        }
    }
}

// ---------------- action head ----------------
__global__ void act_kernel(const float* __restrict__ act_w, const float* __restrict__ act_b,
                           float* __restrict__ out_acts, int t) {
    int idx = blockIdx.x * blockDim.x + threadIdx.x;
    if (idx >= BATCH * ACTD) return;
    int b = idx / ACTD, a = idx % ACTD;
    float s = act_b[a];
    const float* hrow = g_h + (size_t)b * HID;
    const float* wrow = act_w + (size_t)a * HID;
#pragma unroll 8
    for (int k = 0; k < HID; k++) s += hrow[k] * wrow[k];
    out_acts[((size_t)b * TSTEPS + t) * ACTD + a] = s;
}

// ---------------- launch ----------------
extern "C" void kernel_launch(void* const* d_in, const int* in_sizes, int n_in,
                              void* d_out, int out_size) {
    const float* batch = (const float*)d_in[0];
    const float* c1w   = (const float*)d_in[1];
    const float* c1b   = (const float*)d_in[2];
    const float* c2w   = (const float*)d_in[3];
    const float* c2b   = (const float*)d_in[4];
    const float* c3w   = (const float*)d_in[5];
    const float* c3b   = (const float*)d_in[6];
    const float* w_ih  = (const float*)d_in[7];
    const float* w_hh  = (const float*)d_in[8];
    const float* b_ih  = (const float*)d_in[9];
    const float* b_hh  = (const float*)d_in[10];
    const float* msk_w = (const float*)d_in[11];
    const float* msk_b = (const float*)d_in[12];
    const float* act_w = (const float*)d_in[13];
    const float* act_b = (const float*)d_in[14];
    // d_in[15] = length (always 32, compiled in)

    float* out_acts = (float*)d_out;                               // [B,T,26]
    float* out_msks = out_acts + (size_t)BATCH * TSTEPS * ACTD;    // [B,T,30,30]

    const size_t conv_smem = (900 + 8 * 784 + 8 * 676 + 576 + 576) * sizeof(float);
    cudaFuncSetAttribute(conv_kernel, cudaFuncAttributeMaxDynamicSharedMemorySize,
                         (int)conv_smem);

    init_state<<<(BATCH * 900 + 255) / 256, 256>>>();
    transpose_wih<<<FEATSZ * GATESZ / 256, 256>>>(w_ih);
    transpose_whh<<<(HID * GATESZ + 255) / 256, 256>>>(w_hh);
    transpose_wm<<<(HID * 900 + 255) / 256, 256>>>(msk_w);

    for (int t = 0; t < TSTEPS; t++) {
        conv_kernel<<<BATCH, 256, conv_smem>>>(batch, c1w, c1b, c2w, c2b, c3w, c3b);
        gates_gemm<<<dim3(GATESZ / 64, BATCH / 64), 256>>>();
        lstm_pw<<<BATCH * HID / 256, 256>>>(b_ih, b_hh);
        mask_gemm<<<dim3(15, BATCH / 64), 256>>>(msk_b, out_msks, t);
        act_kernel<<<(BATCH * ACTD + 255) / 256, 256>>>(act_w, act_b, out_acts, t);
    }
}

// round 3
// speedup vs baseline: 1.4459x; 1.4459x over previous
#include <cuda_runtime.h>
#include <math.h>

#define BATCH 1024
#define TSTEPS 32
#define HID 128
#define GATESZ 512
#define FEATSZ 4608
#define ACTD 26
#define KTOT (FEATSZ + HID)   // 4736

// ---------------- device scratch (no allocations allowed) ----------------
__device__ float g_msk[BATCH * 900];
__device__ float g_h[BATCH * HID];
__device__ float g_c[BATCH * HID];
__device__ float g_feat[BATCH * FEATSZ];
__device__ float g_gates[BATCH * GATESZ];
__device__ float g_w1t[FEATSZ * GATESZ];    // w_ih^T  [k][n], tf32 bits
__device__ float g_w2t[HID * GATESZ];       // w_hh^T  [k][n], tf32 bits
__device__ float g_wmt[HID * 900];          // msk_w^T [k][n], fp32

__device__ __forceinline__ float sigf(float x) { return 1.f / (1.f + expf(-x)); }

__device__ __forceinline__ unsigned f2tf32(float x) {
    unsigned r;
    asm("cvt.rna.tf32.f32 %0, %1;" : "=r"(r) : "f"(x));
    return r;
}

// ---------------- init state ----------------
__global__ void init_state() {
    int i = blockIdx.x * blockDim.x + threadIdx.x;
    if (i < BATCH * 900) g_msk[i] = 1.f;
    if (i < BATCH * HID) { g_h[i] = 0.f; g_c[i] = 0.f; }
}

// ---------------- weight transposes (+ tf32 convert for gate weights) ------
__global__ void transpose_wih(const float* __restrict__ w) {
    int i = blockIdx.x * 256 + threadIdx.x;
    int k = i / GATESZ, n = i % GATESZ;
    g_w1t[i] = __uint_as_float(f2tf32(w[n * FEATSZ + k]));
}
__global__ void transpose_whh(const float* __restrict__ w) {
    int i = blockIdx.x * 256 + threadIdx.x;
    if (i < HID * GATESZ) {
        int k = i / GATESZ, n = i % GATESZ;
        g_w2t[i] = __uint_as_float(f2tf32(w[n * HID + k]));
    }
}
__global__ void transpose_wm(const float* __restrict__ w) {
    int i = blockIdx.x * 256 + threadIdx.x;
    if (i < HID * 900) {
        int k = i / 900, n = i % 900;
        g_wmt[i] = w[n * HID + k];
    }
}

// ---------------- fused mask-multiply + conv1/2/3 (+ReLU) ----------------
__global__ void conv_kernel(const float* __restrict__ batch,
                            const float* __restrict__ c1w, const float* __restrict__ c1b,
                            const float* __restrict__ c2w, const float* __restrict__ c2b,
                            const float* __restrict__ c3w, const float* __restrict__ c3b) {
    extern __shared__ float sm[];
    float* s_in = sm;                 // 900
    float* s_t1 = sm + 900;           // 8*28*28 = 6272
    float* s_t2 = s_t1 + 6272;        // 8*26*26 = 5408
    float* s_w2 = s_t2 + 5408;        // 576
    float* s_w3 = s_w2 + 576;         // 576

    const int b = blockIdx.x;
    const int tid = threadIdx.x;

    for (int i = tid; i < 900; i += 256) s_in[i] = batch[b * 900 + i] * g_msk[b * 900 + i];
    for (int i = tid; i < 576; i += 256) { s_w2[i] = c2w[i]; s_w3[i] = c3w[i]; }
    __syncthreads();

    const int oc = tid >> 5;
    const int lane = tid & 31;

    // conv1: 1x30x30 -> 8x28x28
    {
        float acc[28];
        float bias = c1b[oc];
#pragma unroll
        for (int r = 0; r < 28; r++) acc[r] = bias;
        float w[9];
#pragma unroll
        for (int i = 0; i < 9; i++) w[i] = c1w[oc * 9 + i];
        if (lane < 28) {
#pragma unroll
            for (int rr = 0; rr < 30; rr++) {
                float i0 = s_in[rr * 30 + lane];
                float i1 = s_in[rr * 30 + lane + 1];
                float i2 = s_in[rr * 30 + lane + 2];
#pragma unroll
                for (int dr = 0; dr < 3; dr++) {
                    int r = rr - dr;
                    if (r >= 0 && r < 28)
                        acc[r] += i0 * w[dr * 3] + i1 * w[dr * 3 + 1] + i2 * w[dr * 3 + 2];
                }
            }
#pragma unroll
            for (int r = 0; r < 28; r++)
                s_t1[oc * 784 + r * 28 + lane] = fmaxf(acc[r], 0.f);
        }
    }
    __syncthreads();

    // conv2: 8x28x28 -> 8x26x26
    {
        float acc[26];
        float bias = c2b[oc];
#pragma unroll
        for (int r = 0; r < 26; r++) acc[r] = bias;
        if (lane < 26) {
            for (int ic = 0; ic < 8; ic++) {
                float w[9];
#pragma unroll
                for (int i = 0; i < 9; i++) w[i] = s_w2[(oc * 8 + ic) * 9 + i];
                const float* inb = s_t1 + ic * 784;
#pragma unroll
                for (int rr = 0; rr < 28; rr++) {
                    float i0 = inb[rr * 28 + lane];
                    float i1 = inb[rr * 28 + lane + 1];
                    float i2 = inb[rr * 28 + lane + 2];
#pragma unroll
                    for (int dr = 0; dr < 3; dr++) {
                        int r = rr - dr;
                        if (r >= 0 && r < 26)
                            acc[r] += i0 * w[dr * 3] + i1 * w[dr * 3 + 1] + i2 * w[dr * 3 + 2];
                    }
                }
            }
#pragma unroll
            for (int r = 0; r < 26; r++)
                s_t2[oc * 676 + r * 26 + lane] = fmaxf(acc[r], 0.f);
        }
    }
    __syncthreads();

    // conv3: 8x26x26 -> 8x24x24 -> g_feat
    {
        float acc[24];
        float bias = c3b[oc];
#pragma unroll
        for (int r = 0; r < 24; r++) acc[r] = bias;
        if (lane < 24) {
            for (int ic = 0; ic < 8; ic++) {
                float w[9];
#pragma unroll
                for (int i = 0; i < 9; i++) w[i] = s_w3[(oc * 8 + ic) * 9 + i];
                const float* inb = s_t2 + ic * 676;
#pragma unroll
                for (int rr = 0; rr < 26; rr++) {
                    float i0 = inb[rr * 26 + lane];
                    float i1 = inb[rr * 26 + lane + 1];
                    float i2 = inb[rr * 26 + lane + 2];
#pragma unroll
                    for (int dr = 0; dr < 3; dr++) {
                        int r = rr - dr;
                        if (r >= 0 && r < 24)
                            acc[r] += i0 * w[dr * 3] + i1 * w[dr * 3 + 1] + i2 * w[dr * 3 + 2];
                    }
                }
            }
#pragma unroll
            for (int r = 0; r < 24; r++)
                g_feat[(size_t)b * FEATSZ + oc * 576 + r * 24 + lane] = fmaxf(acc[r], 0.f);
        }
    }
}

// ---------------- gates GEMM (TF32 tensor cores) ----------------
// [1024,512] = feat[1024,4608] @ w1t + h[1024,128] @ w2t
// Block: 64x64 tile, 128 threads (2x2 warps of 32x32). K-chunks of 32,
// register prefetch of next chunk overlapped with MMA.
__device__ __forceinline__ void mma_tf32(float* c, const unsigned* a, const unsigned* b) {
    asm volatile(
        "mma.sync.aligned.m16n8k8.row.col.f32.tf32.tf32.f32 "
        "{%0,%1,%2,%3}, {%4,%5,%6,%7}, {%8,%9}, {%0,%1,%2,%3};"
        : "+f"(c[0]), "+f"(c[1]), "+f"(c[2]), "+f"(c[3])
        : "r"(a[0]), "r"(a[1]), "r"(a[2]), "r"(a[3]), "r"(b[0]), "r"(b[1]));
}

#define NCHUNK (KTOT / 32)       // 148
#define FCHUNK (FEATSZ / 32)     // 144

__global__ void gates_gemm_tc() {
    __shared__ float As[64 * 36];   // [m][k], stride 36 (bank-free frag reads)
    __shared__ float Bs[32 * 72];   // [k][n], stride 72

    const int tid = threadIdx.x;
    const int m0 = blockIdx.y * 64, n0 = blockIdx.x * 64;
    const int wid = tid >> 5, lane = tid & 31;
    const int wm = (wid >> 1) * 32, wn = (wid & 1) * 32;
    const int grp = lane >> 2, tg = lane & 3;

    float acc[2][4][4];
#pragma unroll
    for (int i = 0; i < 2; i++)
#pragma unroll
        for (int j = 0; j < 4; j++)
#pragma unroll
            for (int e = 0; e < 4; e++) acc[i][j][e] = 0.f;

    // per-thread global load coords
    const int am = tid >> 1;             // 0..63
    const int ak = (tid & 1) * 16;       // 0 or 16
    const int bk = tid >> 2;             // 0..31
    const int bn = (tid & 3) * 16;       // 0,16,32,48

    float4 pa[4], pb[4];

    auto load_chunk = [&](int c) {
        const float* gA;
        if (c < FCHUNK) gA = g_feat + (size_t)(m0 + am) * FEATSZ + c * 32 + ak;
        else            gA = g_h    + (size_t)(m0 + am) * HID   + (c - FCHUNK) * 32 + ak;
#pragma unroll
        for (int i = 0; i < 4; i++) pa[i] = *(const float4*)(gA + 4 * i);
        const float* gB;
        if (c < FCHUNK) gB = g_w1t + (size_t)(c * 32 + bk) * GATESZ + n0 + bn;
        else            gB = g_w2t + (size_t)((c - FCHUNK) * 32 + bk) * GATESZ + n0 + bn;
#pragma unroll
        for (int i = 0; i < 4; i++) pb[i] = *(const float4*)(gB + 4 * i);
    };

    load_chunk(0);

    for (int c = 0; c < NCHUNK; c++) {
        __syncthreads();
        // store A (convert to tf32) and B
#pragma unroll
        for (int i = 0; i < 4; i++) {
            float4 v = pa[i];
            float4 t;
            t.x = __uint_as_float(f2tf32(v.x));
            t.y = __uint_as_float(f2tf32(v.y));
            t.z = __uint_as_float(f2tf32(v.z));
            t.w = __uint_as_float(f2tf32(v.w));
            *(float4*)&As[am * 36 + ak + 4 * i] = t;
            *(float4*)&Bs[bk * 72 + bn + 4 * i] = pb[i];
        }
        __syncthreads();
        if (c + 1 < NCHUNK) load_chunk(c + 1);

#pragma unroll
        for (int kk = 0; kk < 4; kk++) {
            const int kb = kk * 8;
            unsigned a[2][4], b[4][2];
#pragma unroll
            for (int i = 0; i < 2; i++) {
                int r = wm + i * 16 + grp;
                a[i][0] = __float_as_uint(As[r * 36 + kb + tg]);
                a[i][1] = __float_as_uint(As[(r + 8) * 36 + kb + tg]);
                a[i][2] = __float_as_uint(As[r * 36 + kb + tg + 4]);
                a[i][3] = __float_as_uint(As[(r + 8) * 36 + kb + tg + 4]);
            }
#pragma unroll
            for (int j = 0; j < 4; j++) {
                int cn = wn + j * 8 + grp;
                b[j][0] = __float_as_uint(Bs[(kb + tg) * 72 + cn]);
                b[j][1] = __float_as_uint(Bs[(kb + tg + 4) * 72 + cn]);
            }
#pragma unroll
            for (int i = 0; i < 2; i++)
#pragma unroll
                for (int j = 0; j < 4; j++)
                    mma_tf32(acc[i][j], a[i], b[j]);
        }
    }

    // epilogue
#pragma unroll
    for (int i = 0; i < 2; i++) {
#pragma unroll
        for (int j = 0; j < 4; j++) {
            int row = m0 + wm + i * 16 + grp;
            int col = n0 + wn + j * 8 + tg * 2;
            *(float2*)&g_gates[(size_t)row * GATESZ + col] =
                make_float2(acc[i][j][0], acc[i][j][1]);
            *(float2*)&g_gates[(size_t)(row + 8) * GATESZ + col] =
                make_float2(acc[i][j][2], acc[i][j][3]);
        }
    }
}

// ---------------- LSTM pointwise ----------------
__global__ void lstm_pw(const float* __restrict__ b_ih, const float* __restrict__ b_hh) {
    int idx = blockIdx.x * blockDim.x + threadIdx.x;
    int b = idx >> 7, j = idx & 127;
    const float* g = g_gates + (size_t)b * GATESZ;
    float gi = g[j]        + b_ih[j]        + b_hh[j];
    float gf = g[128 + j]  + b_ih[128 + j]  + b_hh[128 + j];
    float gg = g[256 + j]  + b_ih[256 + j]  + b_hh[256 + j];
    float go = g[384 + j]  + b_ih[384 + j]  + b_hh[384 + j];
    float cn = sigf(gf) * g_c[idx] + sigf(gi) * tanhf(gg);
    g_c[idx] = cn;
    g_h[idx] = sigf(go) * tanhf(cn);
}

// ---------------- mask head GEMM + sigmoid ----------------
__global__ void mask_gemm(const float* __restrict__ msk_b, float* __restrict__ out_msks, int t) {
    __shared__ float As[32][65];
    __shared__ float Bs[32][64];
    const int tid = threadIdx.x;
    const int n0 = blockIdx.x * 64, m0 = blockIdx.y * 64;
    const int tx = tid & 15, ty = tid >> 4;
    float acc[4][4] = {};

    for (int k0 = 0; k0 < HID; k0 += 32) {
        __syncthreads();
#pragma unroll
        for (int i = 0; i < 2; i++) {
            int m = (tid >> 3) + i * 32;
            int kk = (tid & 7) * 4;
            float4 v = *(const float4*)(g_h + (size_t)(m0 + m) * HID + k0 + kk);
            As[kk + 0][m] = v.x; As[kk + 1][m] = v.y;
            As[kk + 2][m] = v.z; As[kk + 3][m] = v.w;
        }
#pragma unroll
        for (int i = 0; i < 2; i++) {
            int kk = (tid >> 4) + i * 16;
            int nn = (tid & 15) * 4;
            float4 v = make_float4(0.f, 0.f, 0.f, 0.f);
            if (n0 + nn < 900)
                v = *(const float4*)(g_wmt + (size_t)(k0 + kk) * 900 + n0 + nn);
            *(float4*)&Bs[kk][nn] = v;
        }
        __syncthreads();
#pragma unroll
        for (int k = 0; k < 32; k++) {
            float a0 = As[k][ty * 4 + 0], a1 = As[k][ty * 4 + 1];
            float a2 = As[k][ty * 4 + 2], a3 = As[k][ty * 4 + 3];
            float4 bv = *(const float4*)&Bs[k][tx * 4];
            acc[0][0] += a0 * bv.x; acc[0][1] += a0 * bv.y; acc[0][2] += a0 * bv.z; acc[0][3] += a0 * bv.w;
            acc[1][0] += a1 * bv.x; acc[1][1] += a1 * bv.y; acc[1][2] += a1 * bv.z; acc[1][3] += a1 * bv.w;
            acc[2][0] += a2 * bv.x; acc[2][1] += a2 * bv.y; acc[2][2] += a2 * bv.z; acc[2][3] += a2 * bv.w;
            acc[3][0] += a3 * bv.x; acc[3][1] += a3 * bv.y; acc[3][2] += a3 * bv.z; acc[3][3] += a3 * bv.w;
        }
    }
#pragma unroll
    for (int i = 0; i < 4; i++) {
#pragma unroll
        for (int j = 0; j < 4; j++) {
            int m = m0 + ty * 4 + i;
            int n = n0 + tx * 4 + j;
            if (n < 900) {
                float v = sigf(acc[i][j] + msk_b[n]);
                g_msk[(size_t)m * 900 + n] = v;
                out_msks[((size_t)m * TSTEPS + t) * 900 + n] = v;
            }
        }
    }
}

// ---------------- action head ----------------
__global__ void act_kernel(const float* __restrict__ act_w, const float* __restrict__ act_b,
                           float* __restrict__ out_acts, int t) {
    int idx = blockIdx.x * blockDim.x + threadIdx.x;
    if (idx >= BATCH * ACTD) return;
    int b = idx / ACTD, a = idx % ACTD;
    float s = act_b[a];
    const float* hrow = g_h + (size_t)b * HID;
    const float* wrow = act_w + (size_t)a * HID;
#pragma unroll 8
    for (int k = 0; k < HID; k++) s += hrow[k] * wrow[k];
    out_acts[((size_t)b * TSTEPS + t) * ACTD + a] = s;
}

// ---------------- launch ----------------
extern "C" void kernel_launch(void* const* d_in, const int* in_sizes, int n_in,
                              void* d_out, int out_size) {
    const float* batch = (const float*)d_in[0];
    const float* c1w   = (const float*)d_in[1];
    const float* c1b   = (const float*)d_in[2];
    const float* c2w   = (const float*)d_in[3];
    const float* c2b   = (const float*)d_in[4];
    const float* c3w   = (const float*)d_in[5];
    const float* c3b   = (const float*)d_in[6];
    const float* w_ih  = (const float*)d_in[7];
    const float* w_hh  = (const float*)d_in[8];
    const float* b_ih  = (const float*)d_in[9];
    const float* b_hh  = (const float*)d_in[10];
    const float* msk_w = (const float*)d_in[11];
    const float* msk_b = (const float*)d_in[12];
    const float* act_w = (const float*)d_in[13];
    const float* act_b = (const float*)d_in[14];

    float* out_acts = (float*)d_out;
    float* out_msks = out_acts + (size_t)BATCH * TSTEPS * ACTD;

    const size_t conv_smem = (900 + 8 * 784 + 8 * 676 + 576 + 576) * sizeof(float);
    cudaFuncSetAttribute(conv_kernel, cudaFuncAttributeMaxDynamicSharedMemorySize,
                         (int)conv_smem);

    init_state<<<(BATCH * 900 + 255) / 256, 256>>>();
    transpose_wih<<<FEATSZ * GATESZ / 256, 256>>>(w_ih);
    transpose_whh<<<(HID * GATESZ + 255) / 256, 256>>>(w_hh);
    transpose_wm<<<(HID * 900 + 255) / 256, 256>>>(msk_w);

    for (int t = 0; t < TSTEPS; t++) {
        conv_kernel<<<BATCH, 256, conv_smem>>>(batch, c1w, c1b, c2w, c2b, c3w, c3b);
        gates_gemm_tc<<<dim3(GATESZ / 64, BATCH / 64), 128>>>();
        lstm_pw<<<BATCH * HID / 256, 256>>>(b_ih, b_hh);
        mask_gemm<<<dim3(15, BATCH / 64), 256>>>(msk_b, out_msks, t);
        act_kernel<<<(BATCH * ACTD + 255) / 256, 256>>>(act_w, act_b, out_acts, t);
    }
}

// round 4
// speedup vs baseline: 1.6007x; 1.1071x over previous
#include <cuda_runtime.h>
#include <math.h>

#define BATCH 1024
#define TSTEPS 32
#define HID 128
#define GATESZ 512
#define FEATSZ 4608
#define ACTD 26
#define KTOT (FEATSZ + HID)   // 4736
#define MWID 960              // mask(900) + act(26) + pad, 15*64

// ---------------- device scratch ----------------
__device__ float g_msk[BATCH * 900];
__device__ float g_h[BATCH * HID];
__device__ float g_c[BATCH * HID];
__device__ float g_feat[BATCH * FEATSZ];
__device__ float g_gates[BATCH * GATESZ];
__device__ float g_w1t[FEATSZ * GATESZ];    // w_ih^T  [k][n], tf32 bits
__device__ float g_w2t[HID * GATESZ];       // w_hh^T  [k][n], tf32 bits
__device__ float g_wmt[HID * MWID];         // [msk_w | act_w]^T, fp32

__device__ __forceinline__ float sigf(float x) { return 1.f / (1.f + expf(-x)); }

__device__ __forceinline__ unsigned f2tf32(float x) {
    unsigned r;
    asm("cvt.rna.tf32.f32 %0, %1;" : "=r"(r) : "f"(x));
    return r;
}

// ---- packed fp32x2 helpers (sm_100 dual fp32 FMA) ----
typedef unsigned long long ull;
__device__ __forceinline__ ull pk2(float x, float y) {
    ull r; asm("mov.b64 %0, {%1,%2};" : "=l"(r) : "f"(x), "f"(y)); return r;
}
__device__ __forceinline__ float2 upk2(ull v) {
    float2 f; asm("mov.b64 {%0,%1}, %2;" : "=f"(f.x), "=f"(f.y) : "l"(v)); return f;
}
__device__ __forceinline__ ull fma2(ull a, ull b, ull c) {
    ull d; asm("fma.rn.f32x2 %0, %1, %2, %3;" : "=l"(d) : "l"(a), "l"(b), "l"(c));
    return d;
}

// ---------------- init state ----------------
__global__ void init_state() {
    int i = blockIdx.x * blockDim.x + threadIdx.x;
    if (i < BATCH * 900) g_msk[i] = 1.f;
    if (i < BATCH * HID) { g_h[i] = 0.f; g_c[i] = 0.f; }
}

// ---------------- weight prep ----------------
__global__ void transpose_wih(const float* __restrict__ w) {
    int i = blockIdx.x * 256 + threadIdx.x;
    int k = i / GATESZ, n = i % GATESZ;
    g_w1t[i] = __uint_as_float(f2tf32(w[n * FEATSZ + k]));
}
__global__ void transpose_whh(const float* __restrict__ w) {
    int i = blockIdx.x * 256 + threadIdx.x;
    if (i < HID * GATESZ) {
        int k = i / GATESZ, n = i % GATESZ;
        g_w2t[i] = __uint_as_float(f2tf32(w[n * HID + k]));
    }
}
// combined mask+act weight, [k][n] with n in [0,960)
__global__ void transpose_wm(const float* __restrict__ mw, const float* __restrict__ aw) {
    int i = blockIdx.x * 256 + threadIdx.x;
    if (i < HID * MWID) {
        int k = i / MWID, n = i % MWID;
        float v = 0.f;
        if (n < 900)       v = mw[n * HID + k];
        else if (n < 926)  v = aw[(n - 900) * HID + k];
        g_wmt[i] = v;
    }
}

// ---------------- fused mask-mul + conv1/2/3 (+ReLU), 2 samples/block, f32x2 ----
__global__ void conv_kernel(const float* __restrict__ batch,
                            const float* __restrict__ c1w, const float* __restrict__ c1b,
                            const float* __restrict__ c2w, const float* __restrict__ c2b,
                            const float* __restrict__ c3w, const float* __restrict__ c3b) {
    extern __shared__ float sm[];
    float2* s_in = (float2*)sm;            // 900
    float2* s_t1 = s_in + 900;             // 6272
    float2* s_t2 = s_t1 + 6272;            // 5408
    float*  s_w2 = (float*)(s_t2 + 5408);  // 576
    float*  s_w3 = s_w2 + 576;             // 576

    const int b0 = blockIdx.x * 2, b1 = b0 + 1;
    const int tid = threadIdx.x;

    for (int i = tid; i < 900; i += 256) {
        float lo = batch[b0 * 900 + i] * g_msk[b0 * 900 + i];
        float hi = batch[b1 * 900 + i] * g_msk[b1 * 900 + i];
        s_in[i] = make_float2(lo, hi);
    }
    for (int i = tid; i < 576; i += 256) { s_w2[i] = c2w[i]; s_w3[i] = c3w[i]; }
    __syncthreads();

    const int oc = tid >> 5;
    const int lane = tid & 31;

    // conv1: 1x30x30 -> 8x28x28
    {
        ull acc[28];
        ull bias = pk2(c1b[oc], c1b[oc]);
#pragma unroll
        for (int r = 0; r < 28; r++) acc[r] = bias;
        ull w[9];
#pragma unroll
        for (int i = 0; i < 9; i++) { float v = c1w[oc * 9 + i]; w[i] = pk2(v, v); }
        if (lane < 28) {
#pragma unroll
            for (int rr = 0; rr < 30; rr++) {
                ull i0 = *(const ull*)&s_in[rr * 30 + lane];
                ull i1 = *(const ull*)&s_in[rr * 30 + lane + 1];
                ull i2 = *(const ull*)&s_in[rr * 30 + lane + 2];
#pragma unroll
                for (int dr = 0; dr < 3; dr++) {
                    int r = rr - dr;
                    if (r >= 0 && r < 28) {
                        acc[r] = fma2(i0, w[dr * 3 + 0], acc[r]);
                        acc[r] = fma2(i1, w[dr * 3 + 1], acc[r]);
                        acc[r] = fma2(i2, w[dr * 3 + 2], acc[r]);
                    }
                }
            }
#pragma unroll
            for (int r = 0; r < 28; r++) {
                float2 v = upk2(acc[r]);
                s_t1[oc * 784 + r * 28 + lane] =
                    make_float2(fmaxf(v.x, 0.f), fmaxf(v.y, 0.f));
            }
        }
    }
    __syncthreads();

    // conv2: 8x28x28 -> 8x26x26
    {
        ull acc[26];
        ull bias = pk2(c2b[oc], c2b[oc]);
#pragma unroll
        for (int r = 0; r < 26; r++) acc[r] = bias;
        if (lane < 26) {
            for (int ic = 0; ic < 8; ic++) {
                ull w[9];
#pragma unroll
                for (int i = 0; i < 9; i++) {
                    float v = s_w2[(oc * 8 + ic) * 9 + i];
                    w[i] = pk2(v, v);
                }
                const float2* inb = s_t1 + ic * 784;
#pragma unroll
                for (int rr = 0; rr < 28; rr++) {
                    ull i0 = *(const ull*)&inb[rr * 28 + lane];
                    ull i1 = *(const ull*)&inb[rr * 28 + lane + 1];
                    ull i2 = *(const ull*)&inb[rr * 28 + lane + 2];
#pragma unroll
                    for (int dr = 0; dr < 3; dr++) {
                        int r = rr - dr;
                        if (r >= 0 && r < 26) {
                            acc[r] = fma2(i0, w[dr * 3 + 0], acc[r]);
                            acc[r] = fma2(i1, w[dr * 3 + 1], acc[r]);
                            acc[r] = fma2(i2, w[dr * 3 + 2], acc[r]);
                        }
                    }
                }
            }
#pragma unroll
            for (int r = 0; r < 26; r++) {
                float2 v = upk2(acc[r]);
                s_t2[oc * 676 + r * 26 + lane] =
                    make_float2(fmaxf(v.x, 0.f), fmaxf(v.y, 0.f));
            }
        }
    }
    __syncthreads();

    // conv3: 8x26x26 -> 8x24x24 -> g_feat (two rows)
    {
        ull acc[24];
        ull bias = pk2(c3b[oc], c3b[oc]);
#pragma unroll
        for (int r = 0; r < 24; r++) acc[r] = bias;
        if (lane < 24) {
            for (int ic = 0; ic < 8; ic++) {
                ull w[9];
#pragma unroll
                for (int i = 0; i < 9; i++) {
                    float v = s_w3[(oc * 8 + ic) * 9 + i];
                    w[i] = pk2(v, v);
                }
                const float2* inb = s_t2 + ic * 676;
#pragma unroll
                for (int rr = 0; rr < 26; rr++) {
                    ull i0 = *(const ull*)&inb[rr * 26 + lane];
                    ull i1 = *(const ull*)&inb[rr * 26 + lane + 1];
                    ull i2 = *(const ull*)&inb[rr * 26 + lane + 2];
#pragma unroll
                    for (int dr = 0; dr < 3; dr++) {
                        int r = rr - dr;
                        if (r >= 0 && r < 24) {
                            acc[r] = fma2(i0, w[dr * 3 + 0], acc[r]);
                            acc[r] = fma2(i1, w[dr * 3 + 1], acc[r]);
                            acc[r] = fma2(i2, w[dr * 3 + 2], acc[r]);
                        }
                    }
                }
            }
#pragma unroll
            for (int r = 0; r < 24; r++) {
                float2 v = upk2(acc[r]);
                g_feat[(size_t)b0 * FEATSZ + oc * 576 + r * 24 + lane] = fmaxf(v.x, 0.f);
                g_feat[(size_t)b1 * FEATSZ + oc * 576 + r * 24 + lane] = fmaxf(v.y, 0.f);
            }
        }
    }
}

// ---------------- gates GEMM (TF32 tensor cores) ----------------
__device__ __forceinline__ void mma_tf32(float* c, const unsigned* a, const unsigned* b) {
    asm volatile(
        "mma.sync.aligned.m16n8k8.row.col.f32.tf32.tf32.f32 "
        "{%0,%1,%2,%3}, {%4,%5,%6,%7}, {%8,%9}, {%0,%1,%2,%3};"
        : "+f"(c[0]), "+f"(c[1]), "+f"(c[2]), "+f"(c[3])
        : "r"(a[0]), "r"(a[1]), "r"(a[2]), "r"(a[3]), "r"(b[0]), "r"(b[1]));
}

#define NCHUNK (KTOT / 32)       // 148
#define FCHUNK (FEATSZ / 32)     // 144

__global__ void gates_gemm_tc() {
    __shared__ float As[64 * 36];
    __shared__ float Bs[32 * 72];

    const int tid = threadIdx.x;
    const int m0 = blockIdx.y * 64, n0 = blockIdx.x * 64;
    const int wid = tid >> 5, lane = tid & 31;
    const int wm = (wid >> 1) * 32, wn = (wid & 1) * 32;
    const int grp = lane >> 2, tg = lane & 3;

    float acc[2][4][4];
#pragma unroll
    for (int i = 0; i < 2; i++)
#pragma unroll
        for (int j = 0; j < 4; j++)
#pragma unroll
            for (int e = 0; e < 4; e++) acc[i][j][e] = 0.f;

    const int am = tid >> 1;
    const int ak = (tid & 1) * 16;
    const int bk = tid >> 2;
    const int bn = (tid & 3) * 16;

    float4 pa[4], pb[4];

    auto load_chunk = [&](int c) {
        const float* gA;
        if (c < FCHUNK) gA = g_feat + (size_t)(m0 + am) * FEATSZ + c * 32 + ak;
        else            gA = g_h    + (size_t)(m0 + am) * HID   + (c - FCHUNK) * 32 + ak;
#pragma unroll
        for (int i = 0; i < 4; i++) pa[i] = *(const float4*)(gA + 4 * i);
        const float* gB;
        if (c < FCHUNK) gB = g_w1t + (size_t)(c * 32 + bk) * GATESZ + n0 + bn;
        else            gB = g_w2t + (size_t)((c - FCHUNK) * 32 + bk) * GATESZ + n0 + bn;
#pragma unroll
        for (int i = 0; i < 4; i++) pb[i] = *(const float4*)(gB + 4 * i);
    };

    load_chunk(0);

    for (int c = 0; c < NCHUNK; c++) {
        __syncthreads();
#pragma unroll
        for (int i = 0; i < 4; i++) {
            float4 v = pa[i];
            float4 t;
            t.x = __uint_as_float(f2tf32(v.x));
            t.y = __uint_as_float(f2tf32(v.y));
            t.z = __uint_as_float(f2tf32(v.z));
            t.w = __uint_as_float(f2tf32(v.w));
            *(float4*)&As[am * 36 + ak + 4 * i] = t;
            *(float4*)&Bs[bk * 72 + bn + 4 * i] = pb[i];
        }
        __syncthreads();
        if (c + 1 < NCHUNK) load_chunk(c + 1);

#pragma unroll
        for (int kk = 0; kk < 4; kk++) {
            const int kb = kk * 8;
            unsigned a[2][4], b[4][2];
#pragma unroll
            for (int i = 0; i < 2; i++) {
                int r = wm + i * 16 + grp;
                a[i][0] = __float_as_uint(As[r * 36 + kb + tg]);
                a[i][1] = __float_as_uint(As[(r + 8) * 36 + kb + tg]);
                a[i][2] = __float_as_uint(As[r * 36 + kb + tg + 4]);
                a[i][3] = __float_as_uint(As[(r + 8) * 36 + kb + tg + 4]);
            }
#pragma unroll
            for (int j = 0; j < 4; j++) {
                int cn = wn + j * 8 + grp;
                b[j][0] = __float_as_uint(Bs[(kb + tg) * 72 + cn]);
                b[j][1] = __float_as_uint(Bs[(kb + tg + 4) * 72 + cn]);
            }
#pragma unroll
            for (int i = 0; i < 2; i++)
#pragma unroll
                for (int j = 0; j < 4; j++)
                    mma_tf32(acc[i][j], a[i], b[j]);
        }
    }

#pragma unroll
    for (int i = 0; i < 2; i++) {
#pragma unroll
        for (int j = 0; j < 4; j++) {
            int row = m0 + wm + i * 16 + grp;
            int col = n0 + wn + j * 8 + tg * 2;
            *(float2*)&g_gates[(size_t)row * GATESZ + col] =
                make_float2(acc[i][j][0], acc[i][j][1]);
            *(float2*)&g_gates[(size_t)(row + 8) * GATESZ + col] =
                make_float2(acc[i][j][2], acc[i][j][3]);
        }
    }
}

// ---------------- LSTM pointwise ----------------
__global__ void lstm_pw(const float* __restrict__ b_ih, const float* __restrict__ b_hh) {
    int idx = blockIdx.x * blockDim.x + threadIdx.x;
    int b = idx >> 7, j = idx & 127;
    const float* g = g_gates + (size_t)b * GATESZ;
    float gi = g[j]        + b_ih[j]        + b_hh[j];
    float gf = g[128 + j]  + b_ih[128 + j]  + b_hh[128 + j];
    float gg = g[256 + j]  + b_ih[256 + j]  + b_hh[256 + j];
    float go = g[384 + j]  + b_ih[384 + j]  + b_hh[384 + j];
    float cn = sigf(gf) * g_c[idx] + sigf(gi) * tanhf(gg);
    g_c[idx] = cn;
    g_h[idx] = sigf(go) * tanhf(cn);
}

// ---------------- mask+act head GEMM ----------------
// [1024,960] = h @ g_wmt; cols<900 -> sigmoid -> mask, cols 900..925 -> acts
__global__ void maskact_gemm(const float* __restrict__ msk_b,
                             const float* __restrict__ act_b,
                             float* __restrict__ out_msks,
                             float* __restrict__ out_acts, int t) {
    __shared__ float As[32][65];
    __shared__ float Bs[32][64];
    const int tid = threadIdx.x;
    const int n0 = blockIdx.x * 64, m0 = blockIdx.y * 64;
    const int tx = tid & 15, ty = tid >> 4;
    ull acc2[4][2];
#pragma unroll
    for (int i = 0; i < 4; i++) { acc2[i][0] = 0ULL; acc2[i][1] = 0ULL; }

    for (int k0 = 0; k0 < HID; k0 += 32) {
        __syncthreads();
#pragma unroll
        for (int i = 0; i < 2; i++) {
            int m = (tid >> 3) + i * 32;
            int kk = (tid & 7) * 4;
            float4 v = *(const float4*)(g_h + (size_t)(m0 + m) * HID + k0 + kk);
            As[kk + 0][m] = v.x; As[kk + 1][m] = v.y;
            As[kk + 2][m] = v.z; As[kk + 3][m] = v.w;
        }
#pragma unroll
        for (int i = 0; i < 2; i++) {
            int kk = (tid >> 4) + i * 16;
            int nn = (tid & 15) * 4;
            *(float4*)&Bs[kk][nn] = *(const float4*)(g_wmt + (size_t)(k0 + kk) * MWID + n0 + nn);
        }
        __syncthreads();
#pragma unroll
        for (int k = 0; k < 32; k++) {
            float a0 = As[k][ty * 4 + 0], a1 = As[k][ty * 4 + 1];
            float a2 = As[k][ty * 4 + 2], a3 = As[k][ty * 4 + 3];
            ull b01 = *(const ull*)&Bs[k][tx * 4];
            ull b23 = *(const ull*)&Bs[k][tx * 4 + 2];
            ull A0 = pk2(a0, a0), A1 = pk2(a1, a1), A2 = pk2(a2, a2), A3 = pk2(a3, a3);
            acc2[0][0] = fma2(A0, b01, acc2[0][0]); acc2[0][1] = fma2(A0, b23, acc2[0][1]);
            acc2[1][0] = fma2(A1, b01, acc2[1][0]); acc2[1][1] = fma2(A1, b23, acc2[1][1]);
            acc2[2][0] = fma2(A2, b01, acc2[2][0]); acc2[2][1] = fma2(A2, b23, acc2[2][1]);
            acc2[3][0] = fma2(A3, b01, acc2[3][0]); acc2[3][1] = fma2(A3, b23, acc2[3][1]);
        }
    }
#pragma unroll
    for (int i = 0; i < 4; i++) {
        float vals[4];
        float2 v01 = upk2(acc2[i][0]);
        float2 v23 = upk2(acc2[i][1]);
        vals[0] = v01.x; vals[1] = v01.y; vals[2] = v23.x; vals[3] = v23.y;
        int m = m0 + ty * 4 + i;
#pragma unroll
        for (int j = 0; j < 4; j++) {
            int n = n0 + tx * 4 + j;
            if (n < 900) {
                float v = sigf(vals[j] + msk_b[n]);
                g_msk[(size_t)m * 900 + n] = v;
                out_msks[((size_t)m * TSTEPS + t) * 900 + n] = v;
            } else if (n < 926) {
                out_acts[((size_t)m * TSTEPS + t) * ACTD + (n - 900)] = vals[j] + act_b[n - 900];
            }
        }
    }
}

// ---------------- launch ----------------
extern "C" void kernel_launch(void* const* d_in, const int* in_sizes, int n_in,
                              void* d_out, int out_size) {
    const float* batch = (const float*)d_in[0];
    const float* c1w   = (const float*)d_in[1];
    const float* c1b   = (const float*)d_in[2];
    const float* c2w   = (const float*)d_in[3];
    const float* c2b   = (const float*)d_in[4];
    const float* c3w   = (const float*)d_in[5];
    const float* c3b   = (const float*)d_in[6];
    const float* w_ih  = (const float*)d_in[7];
    const float* w_hh  = (const float*)d_in[8];
    const float* b_ih  = (const float*)d_in[9];
    const float* b_hh  = (const float*)d_in[10];
    const float* msk_w = (const float*)d_in[11];
    const float* msk_b = (const float*)d_in[12];
    const float* act_w = (const float*)d_in[13];
    const float* act_b = (const float*)d_in[14];

    float* out_acts = (float*)d_out;
    float* out_msks = out_acts + (size_t)BATCH * TSTEPS * ACTD;

    const size_t conv_smem = (900 + 6272 + 5408) * sizeof(float2) + 2 * 576 * sizeof(float);
    cudaFuncSetAttribute(conv_kernel, cudaFuncAttributeMaxDynamicSharedMemorySize,
                         (int)conv_smem);

    init_state<<<(BATCH * 900 + 255) / 256, 256>>>();
    transpose_wih<<<FEATSZ * GATESZ / 256, 256>>>(w_ih);
    transpose_whh<<<(HID * GATESZ + 255) / 256, 256>>>(w_hh);
    transpose_wm<<<(HID * MWID + 255) / 256, 256>>>(msk_w, act_w);

    for (int t = 0; t < TSTEPS; t++) {
        conv_kernel<<<BATCH / 2, 256, conv_smem>>>(batch, c1w, c1b, c2w, c2b, c3w, c3b);
        gates_gemm_tc<<<dim3(GATESZ / 64, BATCH / 64), 128>>>();
        lstm_pw<<<BATCH * HID / 256, 256>>>(b_ih, b_hh);
        maskact_gemm<<<dim3(MWID / 64, BATCH / 64), 256>>>(msk_b, act_b, out_msks, out_acts, t);
    }
}

// round 6
// speedup vs baseline: 2.2544x; 1.4084x over previous
#include <cuda_runtime.h>
#include <math.h>

#define BATCH 1024
#define TSTEPS 32
#define HID 128
#define GATESZ 512
#define FEATSZ 4608
#define ACTD 26
#define KTOT (FEATSZ + HID)   // 4736
#define MWID 960              // mask(900) + act(26) + pad

// ---------------- device scratch ----------------
__device__ float g_msk[BATCH * 900];
__device__ float g_h[BATCH * HID];
__device__ float g_c[BATCH * HID];
__device__ float g_feat[BATCH * FEATSZ];
__device__ float g_gates[BATCH * GATESZ];
__device__ float g_w1t[FEATSZ * GATESZ];    // w_ih^T  [k][n], tf32
__device__ float g_w2t[HID * GATESZ];       // w_hh^T  [k][n], tf32
__device__ float g_wmt[HID * MWID];         // [msk_w | act_w]^T, tf32

__device__ __forceinline__ float sigf(float x) { return 1.f / (1.f + expf(-x)); }

__device__ __forceinline__ unsigned f2tf32(float x) {
    unsigned r;
    asm("cvt.rna.tf32.f32 %0, %1;" : "=r"(r) : "f"(x));
    return r;
}

// ---- packed fp32x2 helpers ----
typedef unsigned long long ull;
__device__ __forceinline__ ull pk2(float x, float y) {
    ull r; asm("mov.b64 %0, {%1,%2};" : "=l"(r) : "f"(x), "f"(y)); return r;
}
__device__ __forceinline__ float2 upk2(ull v) {
    float2 f; asm("mov.b64 {%0,%1}, %2;" : "=f"(f.x), "=f"(f.y) : "l"(v)); return f;
}
__device__ __forceinline__ ull fma2(ull a, ull b, ull c) {
    ull d; asm("fma.rn.f32x2 %0, %1, %2, %3;" : "=l"(d) : "l"(a), "l"(b), "l"(c));
    return d;
}

// ---- cp.async helpers ----
__device__ __forceinline__ void cpasync16(float* smem, const float* g) {
    unsigned s = (unsigned)__cvta_generic_to_shared(smem);
    asm volatile("cp.async.cg.shared.global [%0],[%1],16;" :: "r"(s), "l"(g));
}
__device__ __forceinline__ void cp_commit() {
    asm volatile("cp.async.commit_group;");
}
template <int N>
__device__ __forceinline__ void cp_wait() {
    asm volatile("cp.async.wait_group %0;" :: "n"(N));
}

// ---------------- init state ----------------
__global__ void init_state() {
    int i = blockIdx.x * blockDim.x + threadIdx.x;
    if (i < BATCH * 900) g_msk[i] = 1.f;
    if (i < BATCH * HID) { g_h[i] = 0.f; g_c[i] = 0.f; }
}

// ---------------- weight prep ----------------
__global__ void transpose_wih(const float* __restrict__ w) {
    int i = blockIdx.x * 256 + threadIdx.x;
    int k = i / GATESZ, n = i % GATESZ;
    g_w1t[i] = __uint_as_float(f2tf32(w[n * FEATSZ + k]));
}
__global__ void transpose_whh(const float* __restrict__ w) {
    int i = blockIdx.x * 256 + threadIdx.x;
    if (i < HID * GATESZ) {
        int k = i / GATESZ, n = i % GATESZ;
        g_w2t[i] = __uint_as_float(f2tf32(w[n * HID + k]));
    }
}
__global__ void transpose_wm(const float* __restrict__ mw, const float* __restrict__ aw) {
    int i = blockIdx.x * 256 + threadIdx.x;
    if (i < HID * MWID) {
        int k = i / MWID, n = i % MWID;
        float v = 0.f;
        if (n < 900)       v = mw[n * HID + k];
        else if (n < 926)  v = aw[(n - 900) * HID + k];
        g_wmt[i] = __uint_as_float(f2tf32(v));
    }
}

// ---------------- fused mask-mul + conv1/2/3 (+ReLU), 2 samples/block, f32x2 ----
__global__ void conv_kernel(const float* __restrict__ batch,
                            const float* __restrict__ c1w, const float* __restrict__ c1b,
                            const float* __restrict__ c2w, const float* __restrict__ c2b,
                            const float* __restrict__ c3w, const float* __restrict__ c3b) {
    extern __shared__ float sm[];
    float2* s_in = (float2*)sm;            // 900
    float2* s_t1 = s_in + 900;             // 6272
    float2* s_t2 = s_t1 + 6272;            // 5408
    float*  s_w2 = (float*)(s_t2 + 5408);  // 576
    float*  s_w3 = s_w2 + 576;             // 576

    const int b0 = blockIdx.x * 2, b1 = b0 + 1;
    const int tid = threadIdx.x;

    for (int i = tid; i < 900; i += 256) {
        float lo = batch[b0 * 900 + i] * g_msk[b0 * 900 + i];
        float hi = batch[b1 * 900 + i] * g_msk[b1 * 900 + i];
        s_in[i] = make_float2(lo, hi);
    }
    for (int i = tid; i < 576; i += 256) { s_w2[i] = c2w[i]; s_w3[i] = c3w[i]; }
    __syncthreads();

    const int oc = tid >> 5;
    const int lane = tid & 31;

    // conv1
    {
        ull acc[28];
        ull bias = pk2(c1b[oc], c1b[oc]);
#pragma unroll
        for (int r = 0; r < 28; r++) acc[r] = bias;
        ull w[9];
#pragma unroll
        for (int i = 0; i < 9; i++) { float v = c1w[oc * 9 + i]; w[i] = pk2(v, v); }
        if (lane < 28) {
#pragma unroll
            for (int rr = 0; rr < 30; rr++) {
                ull i0 = *(const ull*)&s_in[rr * 30 + lane];
                ull i1 = *(const ull*)&s_in[rr * 30 + lane + 1];
                ull i2 = *(const ull*)&s_in[rr * 30 + lane + 2];
#pragma unroll
                for (int dr = 0; dr < 3; dr++) {
                    int r = rr - dr;
                    if (r >= 0 && r < 28) {
                        acc[r] = fma2(i0, w[dr * 3 + 0], acc[r]);
                        acc[r] = fma2(i1, w[dr * 3 + 1], acc[r]);
                        acc[r] = fma2(i2, w[dr * 3 + 2], acc[r]);
                    }
                }
            }
#pragma unroll
            for (int r = 0; r < 28; r++) {
                float2 v = upk2(acc[r]);
                s_t1[oc * 784 + r * 28 + lane] =
                    make_float2(fmaxf(v.x, 0.f), fmaxf(v.y, 0.f));
            }
        }
    }
    __syncthreads();

    // conv2
    {
        ull acc[26];
        ull bias = pk2(c2b[oc], c2b[oc]);
#pragma unroll
        for (int r = 0; r < 26; r++) acc[r] = bias;
        if (lane < 26) {
            for (int ic = 0; ic < 8; ic++) {
                ull w[9];
#pragma unroll
                for (int i = 0; i < 9; i++) {
                    float v = s_w2[(oc * 8 + ic) * 9 + i];
                    w[i] = pk2(v, v);
                }
                const float2* inb = s_t1 + ic * 784;
#pragma unroll
                for (int rr = 0; rr < 28; rr++) {
                    ull i0 = *(const ull*)&inb[rr * 28 + lane];
                    ull i1 = *(const ull*)&inb[rr * 28 + lane + 1];
                    ull i2 = *(const ull*)&inb[rr * 28 + lane + 2];
#pragma unroll
                    for (int dr = 0; dr < 3; dr++) {
                        int r = rr - dr;
                        if (r >= 0 && r < 26) {
                            acc[r] = fma2(i0, w[dr * 3 + 0], acc[r]);
                            acc[r] = fma2(i1, w[dr * 3 + 1], acc[r]);
                            acc[r] = fma2(i2, w[dr * 3 + 2], acc[r]);
                        }
                    }
                }
            }
#pragma unroll
            for (int r = 0; r < 26; r++) {
                float2 v = upk2(acc[r]);
                s_t2[oc * 676 + r * 26 + lane] =
                    make_float2(fmaxf(v.x, 0.f), fmaxf(v.y, 0.f));
            }
        }
    }
    __syncthreads();

    // conv3
    {
        ull acc[24];
        ull bias = pk2(c3b[oc], c3b[oc]);
#pragma unroll
        for (int r = 0; r < 24; r++) acc[r] = bias;
        if (lane < 24) {
            for (int ic = 0; ic < 8; ic++) {
                ull w[9];
#pragma unroll
                for (int i = 0; i < 9; i++) {
                    float v = s_w3[(oc * 8 + ic) * 9 + i];
                    w[i] = pk2(v, v);
                }
                const float2* inb = s_t2 + ic * 676;
#pragma unroll
                for (int rr = 0; rr < 26; rr++) {
                    ull i0 = *(const ull*)&inb[rr * 26 + lane];
                    ull i1 = *(const ull*)&inb[rr * 26 + lane + 1];
                    ull i2 = *(const ull*)&inb[rr * 26 + lane + 2];
#pragma unroll
                    for (int dr = 0; dr < 3; dr++) {
                        int r = rr - dr;
                        if (r >= 0 && r < 24) {
                            acc[r] = fma2(i0, w[dr * 3 + 0], acc[r]);
                            acc[r] = fma2(i1, w[dr * 3 + 1], acc[r]);
                            acc[r] = fma2(i2, w[dr * 3 + 2], acc[r]);
                        }
                    }
                }
            }
#pragma unroll
            for (int r = 0; r < 24; r++) {
                float2 v = upk2(acc[r]);
                g_feat[(size_t)b0 * FEATSZ + oc * 576 + r * 24 + lane] = fmaxf(v.x, 0.f);
                g_feat[(size_t)b1 * FEATSZ + oc * 576 + r * 24 + lane] = fmaxf(v.y, 0.f);
            }
        }
    }
}

// ---------------- TF32 MMA ----------------
__device__ __forceinline__ void mma_tf32(float* c, const unsigned* a, const unsigned* b) {
    asm volatile(
        "mma.sync.aligned.m16n8k8.row.col.f32.tf32.tf32.f32 "
        "{%0,%1,%2,%3}, {%4,%5,%6,%7}, {%8,%9}, {%0,%1,%2,%3};"
        : "+f"(c[0]), "+f"(c[1]), "+f"(c[2]), "+f"(c[3])
        : "r"(a[0]), "r"(a[1]), "r"(a[2]), "r"(a[3]), "r"(b[0]), "r"(b[1]));
}

// ---------------- gates GEMM: cp.async 2-stage, chunk K=64 ----------------
#define GCH 64
#define NCH (KTOT / GCH)    // 74
#define FCH (FEATSZ / GCH)  // 72
#define AS_STRIDE 68
#define BS_STRIDE 72
#define AS_SZ (64 * AS_STRIDE)   // 4352 floats
#define BS_SZ (64 * BS_STRIDE)   // 4608 floats
#define GATES_SMEM ((2 * AS_SZ + 2 * BS_SZ) * sizeof(float))  // 71680 B

__global__ void __launch_bounds__(128) gates_gemm_tc() {
    extern __shared__ float smem[];
    float* As[2] = { smem, smem + AS_SZ };
    float* Bs[2] = { smem + 2 * AS_SZ, smem + 2 * AS_SZ + BS_SZ };

    const int tid = threadIdx.x;
    const int m0 = blockIdx.y * 64, n0 = blockIdx.x * 64;
    const int wid = tid >> 5, lane = tid & 31;
    const int wm = (wid >> 1) * 32, wn = (wid & 1) * 32;
    const int grp = lane >> 2, tg = lane & 3;

    float acc[2][4][4];
#pragma unroll
    for (int i = 0; i < 2; i++)
#pragma unroll
        for (int j = 0; j < 4; j++)
#pragma unroll
            for (int e = 0; e < 4; e++) acc[i][j][e] = 0.f;

    auto issue = [&](int c, int st) {
        float* a = As[st];
        float* b = Bs[st];
#pragma unroll
        for (int i = 0; i < 8; i++) {
            int s = i * 128 + tid;            // 0..1023 (16B segs)
            int row = s >> 4, cs = (s & 15) * 4;
            const float* ga = (c < FCH)
                ? g_feat + (size_t)(m0 + row) * FEATSZ + c * GCH + cs
                : g_h    + (size_t)(m0 + row) * HID + (c - FCH) * GCH + cs;
            cpasync16(a + row * AS_STRIDE + cs, ga);
            const float* gb = (c < FCH)
                ? g_w1t + (size_t)(c * GCH + row) * GATESZ + n0 + cs
                : g_w2t + (size_t)((c - FCH) * GCH + row) * GATESZ + n0 + cs;
            cpasync16(b + row * BS_STRIDE + cs, gb);
        }
    };

    issue(0, 0);
    cp_commit();

    for (int c = 0; c < NCH; c++) {
        if (c + 1 < NCH) {
            issue(c + 1, (c + 1) & 1);
            cp_commit();
            cp_wait<1>();
        } else {
            cp_wait<0>();
        }
        __syncthreads();

        const float* a_s = As[c & 1];
        const float* b_s = Bs[c & 1];
#pragma unroll
        for (int kk = 0; kk < 8; kk++) {
            const int kb = kk * 8;
            unsigned a[2][4], b[4][2];
#pragma unroll
            for (int i = 0; i < 2; i++) {
                int r = wm + i * 16 + grp;
                a[i][0] = __float_as_uint(a_s[r * AS_STRIDE + kb + tg]);
                a[i][1] = __float_as_uint(a_s[(r + 8) * AS_STRIDE + kb + tg]);
                a[i][2] = __float_as_uint(a_s[r * AS_STRIDE + kb + tg + 4]);
                a[i][3] = __float_as_uint(a_s[(r + 8) * AS_STRIDE + kb + tg + 4]);
            }
#pragma unroll
            for (int j = 0; j < 4; j++) {
                int cn = wn + j * 8 + grp;
                b[j][0] = __float_as_uint(b_s[(kb + tg) * BS_STRIDE + cn]);
                b[j][1] = __float_as_uint(b_s[(kb + tg + 4) * BS_STRIDE + cn]);
            }
#pragma unroll
            for (int i = 0; i < 2; i++)
#pragma unroll
                for (int j = 0; j < 4; j++)
                    mma_tf32(acc[i][j], a[i], b[j]);
        }
        __syncthreads();
    }

#pragma unroll
    for (int i = 0; i < 2; i++) {
#pragma unroll
        for (int j = 0; j < 4; j++) {
            int row = m0 + wm + i * 16 + grp;
            int col = n0 + wn + j * 8 + tg * 2;
            *(float2*)&g_gates[(size_t)row * GATESZ + col] =
                make_float2(acc[i][j][0], acc[i][j][1]);
            *(float2*)&g_gates[(size_t)(row + 8) * GATESZ + col] =
                make_float2(acc[i][j][2], acc[i][j][3]);
        }
    }
}

// ---------------- LSTM pointwise ----------------
__global__ void lstm_pw(const float* __restrict__ b_ih, const float* __restrict__ b_hh) {
    int idx = blockIdx.x * blockDim.x + threadIdx.x;
    int b = idx >> 7, j = idx & 127;
    const float* g = g_gates + (size_t)b * GATESZ;
    float gi = g[j]        + b_ih[j]        + b_hh[j];
    float gf = g[128 + j]  + b_ih[128 + j]  + b_hh[128 + j];
    float gg = g[256 + j]  + b_ih[256 + j]  + b_hh[256 + j];
    float go = g[384 + j]  + b_ih[384 + j]  + b_hh[384 + j];
    float cn = sigf(gf) * g_c[idx] + sigf(gi) * tanhf(gg);
    g_c[idx] = cn;
    g_h[idx] = sigf(go) * tanhf(cn);
}

// ---------------- mask+act head GEMM (TF32 MMA, single-shot K=128) ----------------
#define MAS_STRIDE 132
#define MAS_SZ (64 * MAS_STRIDE)    // 8448 floats
#define MBS_SZ (128 * BS_STRIDE)    // 9216 floats
#define MASK_SMEM ((MAS_SZ + MBS_SZ) * sizeof(float))   // 70656 B

__global__ void __launch_bounds__(128) maskact_gemm(const float* __restrict__ msk_b,
                                                    const float* __restrict__ act_b,
                                                    float* __restrict__ out_msks,
                                                    float* __restrict__ out_acts, int t) {
    extern __shared__ float smem[];
    float* As = smem;               // [m][k] 64 x 132
    float* Bs = smem + MAS_SZ;      // [k][n] 128 x 72

    const int tid = threadIdx.x;
    const int n0 = blockIdx.x * 64, m0 = blockIdx.y * 64;
    const int wid = tid >> 5, lane = tid & 31;
    const int wm = (wid >> 1) * 32, wn = (wid & 1) * 32;
    const int grp = lane >> 2, tg = lane & 3;

    // A: 64 rows x 128 cols = 2048 16B-segs; 16 per thread
#pragma unroll
    for (int i = 0; i < 16; i++) {
        int s = i * 128 + tid;
        int row = s >> 5, cs = (s & 31) * 4;
        cpasync16(As + row * MAS_STRIDE + cs, g_h + (size_t)(m0 + row) * HID + cs);
    }
    // B: 128 rows x 64 cols = 2048 16B-segs; 16 per thread  (FIXED: was 8)
#pragma unroll
    for (int i = 0; i < 16; i++) {
        int s = i * 128 + tid;
        int row = s >> 4, cs = (s & 15) * 4;    // row 0..127, cs 0..60
        cpasync16(Bs + row * BS_STRIDE + cs, g_wmt + (size_t)row * MWID + n0 + cs);
    }
    cp_commit();
    cp_wait<0>();
    __syncthreads();

    float acc[2][4][4];
#pragma unroll
    for (int i = 0; i < 2; i++)
#pragma unroll
        for (int j = 0; j < 4; j++)
#pragma unroll
            for (int e = 0; e < 4; e++) acc[i][j][e] = 0.f;

#pragma unroll
    for (int kk = 0; kk < 16; kk++) {
        const int kb = kk * 8;
        unsigned a[2][4], b[4][2];
#pragma unroll
        for (int i = 0; i < 2; i++) {
            int r = wm + i * 16 + grp;
            a[i][0] = __float_as_uint(As[r * MAS_STRIDE + kb + tg]);
            a[i][1] = __float_as_uint(As[(r + 8) * MAS_STRIDE + kb + tg]);
            a[i][2] = __float_as_uint(As[r * MAS_STRIDE + kb + tg + 4]);
            a[i][3] = __float_as_uint(As[(r + 8) * MAS_STRIDE + kb + tg + 4]);
        }
#pragma unroll
        for (int j = 0; j < 4; j++) {
            int cn = wn + j * 8 + grp;
            b[j][0] = __float_as_uint(Bs[(kb + tg) * BS_STRIDE + cn]);
            b[j][1] = __float_as_uint(Bs[(kb + tg + 4) * BS_STRIDE + cn]);
        }
#pragma unroll
        for (int i = 0; i < 2; i++)
#pragma unroll
            for (int j = 0; j < 4; j++)
                mma_tf32(acc[i][j], a[i], b[j]);
    }

    // epilogue: sigmoid->mask for n<900, acts for 900..925
#pragma unroll
    for (int i = 0; i < 2; i++) {
#pragma unroll
        for (int j = 0; j < 4; j++) {
            int row = m0 + wm + i * 16 + grp;
            int col = n0 + wn + j * 8 + tg * 2;
#pragma unroll
            for (int e = 0; e < 4; e++) {
                int m = row + (e >> 1) * 8;
                int n = col + (e & 1);
                float x = acc[i][j][e];
                if (n < 900) {
                    float v = sigf(x + msk_b[n]);
                    g_msk[(size_t)m * 900 + n] = v;
                    out_msks[((size_t)m * TSTEPS + t) * 900 + n] = v;
                } else if (n < 926) {
                    out_acts[((size_t)m * TSTEPS + t) * ACTD + (n - 900)] = x + act_b[n - 900];
                }
            }
        }
    }
}

// ---------------- launch ----------------
extern "C" void kernel_launch(void* const* d_in, const int* in_sizes, int n_in,
                              void* d_out, int out_size) {
    const float* batch = (const float*)d_in[0];
    const float* c1w   = (const float*)d_in[1];
    const float* c1b   = (const float*)d_in[2];
    const float* c2w   = (const float*)d_in[3];
    const float* c2b   = (const float*)d_in[4];
    const float* c3w   = (const float*)d_in[5];
    const float* c3b   = (const float*)d_in[6];
    const float* w_ih  = (const float*)d_in[7];
    const float* w_hh  = (const float*)d_in[8];
    const float* b_ih  = (const float*)d_in[9];
    const float* b_hh  = (const float*)d_in[10];
    const float* msk_w = (const float*)d_in[11];
    const float* msk_b = (const float*)d_in[12];
    const float* act_w = (const float*)d_in[13];
    const float* act_b = (const float*)d_in[14];

    float* out_acts = (float*)d_out;
    float* out_msks = out_acts + (size_t)BATCH * TSTEPS * ACTD;

    const size_t conv_smem = (900 + 6272 + 5408) * sizeof(float2) + 2 * 576 * sizeof(float);
    cudaFuncSetAttribute(conv_kernel, cudaFuncAttributeMaxDynamicSharedMemorySize,
                         (int)conv_smem);
    cudaFuncSetAttribute(gates_gemm_tc, cudaFuncAttributeMaxDynamicSharedMemorySize,
                         (int)GATES_SMEM);
    cudaFuncSetAttribute(maskact_gemm, cudaFuncAttributeMaxDynamicSharedMemorySize,
                         (int)MASK_SMEM);

    init_state<<<(BATCH * 900 + 255) / 256, 256>>>();
    transpose_wih<<<FEATSZ * GATESZ / 256, 256>>>(w_ih);
    transpose_whh<<<(HID * GATESZ + 255) / 256, 256>>>(w_hh);
    transpose_wm<<<(HID * MWID + 255) / 256, 256>>>(msk_w, act_w);

    for (int t = 0; t < TSTEPS; t++) {
        conv_kernel<<<BATCH / 2, 256, conv_smem>>>(batch, c1w, c1b, c2w, c2b, c3w, c3b);
        gates_gemm_tc<<<dim3(GATESZ / 64, BATCH / 64), 128, GATES_SMEM>>>();
        lstm_pw<<<BATCH * HID / 256, 256>>>(b_ih, b_hh);
        maskact_gemm<<<dim3(MWID / 64, BATCH / 64), 128, MASK_SMEM>>>(msk_b, act_b,
                                                                      out_msks, out_acts, t);
    }
}